// round 15
// baseline (speedup 1.0000x reference)
#include <cuda_runtime.h>
#include <cuda_bf16.h>
#include <math.h>
#include <stdint.h>

// Problem constants
#define BB   1024
#define SS   49
#define DD   128
#define HH   4
#define VV   100001
#define VV_PAD 100096            // 782 * 128
#define BS   (BB*SS)             // 50176
#define NEGV (-1e8f)

typedef unsigned long long ull;

// =====================================================================
// scratch (device globals: no allocs allowed)
// =====================================================================
__device__ __align__(256) __nv_bfloat16 g_x   [BS * DD];              // embedded bf16
__device__ __align__(256) __nv_bfloat16 g_qkv [BS * 3 * DD];          // q|k|v concat bf16, ld=384
__device__ __align__(256) __nv_bfloat16 g_av  [BS * DD];              // attention out, bf16
__device__ __align__(256) __nv_bfloat16 g_enc [BS * DD];              // encoder out, bf16
__device__ __align__(256) __nv_bfloat16 g_p   [BB * DD];              // pooled, bf16
__device__ __align__(256) __nv_bfloat16 g_ws  [(size_t)VV_PAD * DD];  // w_score^T [n][k] bf16
__device__ __align__(256) __nv_bfloat16 g_w4  [4][DD * DD];           // wq,wk,wv,wo ^T bf16
__device__ __align__(256) float         g_b3  [3 * DD];               // bq|bk|bv concat

// =====================================================================
// PTX helpers
// =====================================================================
__device__ __forceinline__ void mma_bf16(float* c, const uint32_t* a, const uint32_t* b) {
    asm volatile(
        "mma.sync.aligned.m16n8k16.row.col.f32.bf16.bf16.f32 "
        "{%0,%1,%2,%3}, {%4,%5,%6,%7}, {%8,%9}, {%0,%1,%2,%3};"
        : "+f"(c[0]), "+f"(c[1]), "+f"(c[2]), "+f"(c[3])
        : "r"(a[0]), "r"(a[1]), "r"(a[2]), "r"(a[3]), "r"(b[0]), "r"(b[1]));
}
__device__ __forceinline__ uint32_t cvta_smem(const void* p) {
    uint32_t a;
    asm("{ .reg .u64 t; cvta.to.shared.u64 t, %1; cvt.u32.u64 %0, t; }"
        : "=r"(a) : "l"(p));
    return a;
}
__device__ __forceinline__ void ldsm_x4(uint32_t* r, uint32_t addr) {
    asm volatile("ldmatrix.sync.aligned.m8n8.x4.shared.b16 {%0,%1,%2,%3}, [%4];"
                 : "=r"(r[0]), "=r"(r[1]), "=r"(r[2]), "=r"(r[3]) : "r"(addr));
}
__device__ __forceinline__ void cp16(uint32_t s, const void* g) {
    asm volatile("cp.async.ca.shared.global [%0], [%1], 16;" :: "r"(s), "l"(g));
}
#define CP_COMMIT() asm volatile("cp.async.commit_group;" ::: "memory")
#define CP_WAIT0()  asm volatile("cp.async.wait_group 0;" ::: "memory")

// smem tile geometry: rows x 128 bf16, padded row stride = 272 bytes
#define ROWB 272
#define TILE_A_SMEM (64 * ROWB)    // 17408
#define TILE_B_SMEM (128 * ROWB)   // 34816
#define CSTAGE_LD   132            // fp32 staging row stride (words)

// =====================================================================
// K1 (merged prep): embed+PE | w_score transpose | w4 transpose | bias3
// =====================================================================
#define PREP_EMBED  BS                     // 50176
#define PREP_WSV    (VV_PAD / 32)          // 3128
__global__ __launch_bounds__(128)
void prep_kernel(const int* __restrict__ seq, const int* __restrict__ sub,
                 const float* __restrict__ emb, const float* __restrict__ sgt,
                 const float* __restrict__ wscore,
                 const float* __restrict__ w0, const float* __restrict__ w1,
                 const float* __restrict__ w2, const float* __restrict__ w3,
                 const float* __restrict__ bq, const float* __restrict__ bk,
                 const float* __restrict__ bv,
                 __nv_bfloat16* __restrict__ x, __nv_bfloat16* __restrict__ ws,
                 __nv_bfloat16* __restrict__ w4, float* __restrict__ b3)
{
    __shared__ float st[32][129];
    const int bid = blockIdx.x;
    const int t = threadIdx.x;

    if (bid < PREP_EMBED) {
        int bs = bid;
        int s  = bs % SS;
        int item = seq[bs];
        int stype = sub[bs];
        float pe = (t & 1) ? cosf((float)s) : sinf((float)s);
        float v  = emb[(size_t)item * DD + t] + sgt[(size_t)stype * DD + t] + pe;
        x[(size_t)bs * DD + t] = __float2bfloat16(v);
        return;
    }
    if (bid < PREP_EMBED + PREP_WSV) {
        int n0 = (bid - PREP_EMBED) * 32;
        #pragma unroll
        for (int rep = 0; rep < 32; rep++) {
            int i = rep * 128 + t;
            int k = i >> 5, j = i & 31;
            int n = n0 + j;
            st[j][k] = (n < VV) ? wscore[(size_t)k * VV + n] : 0.f;
        }
        __syncthreads();
        #pragma unroll
        for (int rep = 0; rep < 32; rep++) {
            int i = rep * 128 + t;
            int nl = i >> 7, k = i & 127;
            ws[(size_t)(n0 + nl) * DD + k] = __float2bfloat16(st[nl][k]);
        }
        return;
    }
    if (bid < PREP_EMBED + PREP_WSV + 16) {
        int r  = bid - PREP_EMBED - PREP_WSV;
        int w  = r >> 2;
        int n0 = (r & 3) * 32;
        const float* W = (w == 0) ? w0 : (w == 1) ? w1 : (w == 2) ? w2 : w3;
        __nv_bfloat16* T = w4 + (size_t)w * DD * DD;
        #pragma unroll
        for (int rep = 0; rep < 32; rep++) {
            int i = rep * 128 + t;
            int k = i >> 5, j = i & 31;
            st[j][k] = W[(size_t)k * DD + n0 + j];
        }
        __syncthreads();
        #pragma unroll
        for (int rep = 0; rep < 32; rep++) {
            int i = rep * 128 + t;
            int nl = i >> 7, k = i & 127;
            T[(size_t)(n0 + nl) * DD + k] = __float2bfloat16(st[nl][k]);
        }
        return;
    }
    for (int i = t; i < 384; i += 128)
        b3[i] = (i < 128) ? bq[i] : (i < 256) ? bk[i - 128] : bv[i - 256];
}

// =====================================================================
// K2: bf16 tensor-core GEMM (warp tile 32x32, CTA 64x128).
// bf16 output: double-buffered A + direct bf16x2 stores.
// fp32 output: single A buffer, next-A cp.async issued BEFORE the staged
//   epilogue (load hides under the 32KB coalesced store phase).
// =====================================================================
template<typename OutT>
__global__ __launch_bounds__(256, 3)
void mma_gemm(const __nv_bfloat16* __restrict__ A, const __nv_bfloat16* __restrict__ B,
              const float* __restrict__ bias, OutT* __restrict__ C,
              long long ldc, int nvalid, int m_iters)
{
    extern __shared__ char sm[];
    char* sB    = sm;
    char* sAbuf = sB + TILE_B_SMEM;                 // 2 x TILE_A_SMEM region
    float* sbias = (float*)(sAbuf + 2 * TILE_A_SMEM);
    float* sC    = (float*)(sAbuf + TILE_A_SMEM);   // fp32 path: 32x132 staging

    const int t = threadIdx.x;
    const int lane = t & 31;
    const int wid  = t >> 5;
    const int warp_m = wid >> 2;        // 0..1 (32 rows each)
    const int warp_n = wid & 3;         // 0..3 (32 cols each)
    const int n0 = blockIdx.x * 128;

    const uint32_t sBu = cvta_smem(sB);
    const uint32_t sAu = cvta_smem(sAbuf);

    // ---- async load B tile + first A tile ----
    {
        const __nv_bfloat16* gB = B + (size_t)n0 * DD;
        #pragma unroll
        for (int i = 0; i < 8; i++) {
            int idx = i * 256 + t;
            int r = idx >> 4, seg = idx & 15;
            cp16(sBu + r * ROWB + seg * 16, gB + (size_t)r * DD + seg * 8);
        }
        const __nv_bfloat16* gA = A + (size_t)(blockIdx.y * m_iters) * 64 * DD;
        #pragma unroll
        for (int i = 0; i < 4; i++) {
            int idx = i * 256 + t;
            int r = idx >> 4, seg = idx & 15;
            cp16(sAu + r * ROWB + seg * 16, gA + (size_t)r * DD + seg * 8);
        }
        CP_COMMIT();
        if (t < 128) sbias[t] = (n0 + t < nvalid) ? bias[n0 + t] : 0.f;
        CP_WAIT0();
    }
    __syncthreads();

    // ---- ldmatrix lane addressing ----
    const int quad = lane >> 3, j = lane & 7;
    const uint32_t aLane = (uint32_t)((warp_m * 32 + (quad & 1) * 8 + j) * ROWB
                                      + (quad >> 1) * 16);
    const uint32_t bLane = sBu
                         + (uint32_t)((warp_n * 32 + (quad >> 1) * 8 + j) * ROWB
                                      + (quad & 1) * 16);

    const int frow = lane >> 2;
    int cur = 0;

    for (int iter = 0; iter < m_iters; iter++) {
        const int m0 = (blockIdx.y * m_iters + iter) * 64;
        const bool has_next = (iter + 1 < m_iters);

        if constexpr (sizeof(OutT) == 2) {
            if (has_next) {
                const __nv_bfloat16* gn = A + (size_t)(m0 + 64) * DD;
                const uint32_t dst = sAu + (uint32_t)((cur ^ 1) * TILE_A_SMEM);
                #pragma unroll
                for (int i = 0; i < 4; i++) {
                    int idx = i * 256 + t;
                    int r = idx >> 4, seg = idx & 15;
                    cp16(dst + r * ROWB + seg * 16, gn + (size_t)r * DD + seg * 8);
                }
                CP_COMMIT();
            }
        }

        const uint32_t aAddr = aLane + sAu + (uint32_t)(cur * TILE_A_SMEM);

        float acc[2][4][4];
        #pragma unroll
        for (int mi = 0; mi < 2; mi++)
            #pragma unroll
            for (int ni = 0; ni < 4; ni++)
                #pragma unroll
                for (int e = 0; e < 4; e++) acc[mi][ni][e] = 0.f;

        #pragma unroll
        for (int kb = 0; kb < 8; kb++) {
            const uint32_t ko = kb * 32;
            uint32_t a0[4], a1[4], b01[4], b23[4];
            ldsm_x4(a0,  aAddr + ko);
            ldsm_x4(a1,  aAddr + ko + 16 * ROWB);
            ldsm_x4(b01, bLane + ko);
            ldsm_x4(b23, bLane + ko + 16 * ROWB);
            mma_bf16(acc[0][0], a0, b01);  mma_bf16(acc[0][1], a0, b01 + 2);
            mma_bf16(acc[0][2], a0, b23);  mma_bf16(acc[0][3], a0, b23 + 2);
            mma_bf16(acc[1][0], a1, b01);  mma_bf16(acc[1][1], a1, b01 + 2);
            mma_bf16(acc[1][2], a1, b23);  mma_bf16(acc[1][3], a1, b23 + 2);
        }

        if constexpr (sizeof(OutT) == 2) {
            #pragma unroll
            for (int mi = 0; mi < 2; mi++) {
                const int r0 = m0 + warp_m * 32 + mi * 16 + frow;
                OutT* crow0 = C + (long long)r0 * ldc;
                OutT* crow1 = C + (long long)(r0 + 8) * ldc;
                #pragma unroll
                for (int ni = 0; ni < 4; ni++) {
                    const int nl = warp_n * 32 + ni * 8 + (lane & 3) * 2;
                    const int n  = n0 + nl;
                    const float b0 = sbias[nl], b1 = sbias[nl + 1];
                    __nv_bfloat162 s0, s1;
                    s0.x = __float2bfloat16(acc[mi][ni][0] + b0);
                    s0.y = __float2bfloat16(acc[mi][ni][1] + b1);
                    s1.x = __float2bfloat16(acc[mi][ni][2] + b0);
                    s1.y = __float2bfloat16(acc[mi][ni][3] + b1);
                    *reinterpret_cast<__nv_bfloat162*>(crow0 + n) = s0;
                    *reinterpret_cast<__nv_bfloat162*>(crow1 + n) = s1;
                }
            }
            if (has_next) {
                CP_WAIT0();
                __syncthreads();
                cur ^= 1;
            }
        } else {
            // ---- issue next-A load NOW (hides under epilogue stores) ----
            if (has_next) {
                __syncthreads();   // all ldmatrix reads of sA complete
                const __nv_bfloat16* gn = A + (size_t)(m0 + 64) * DD;
                #pragma unroll
                for (int i = 0; i < 4; i++) {
                    int idx = i * 256 + t;
                    int r = idx >> 4, seg = idx & 15;
                    cp16(sAu + r * ROWB + seg * 16, gn + (size_t)r * DD + seg * 8);
                }
                CP_COMMIT();
            }
            // ---- fp32 epilogue: smem-staged, coalesced stores ----
            #pragma unroll
            for (int h = 0; h < 2; h++) {
                __syncthreads();
                if (warp_m == h) {
                    #pragma unroll
                    for (int mi = 0; mi < 2; mi++) {
                        const int lr = mi * 16 + frow;
                        #pragma unroll
                        for (int ni = 0; ni < 4; ni++) {
                            const int nl = warp_n * 32 + ni * 8 + (lane & 3) * 2;
                            const float b0 = sbias[nl], b1 = sbias[nl + 1];
                            sC[lr * CSTAGE_LD + nl]           = acc[mi][ni][0] + b0;
                            sC[lr * CSTAGE_LD + nl + 1]       = acc[mi][ni][1] + b1;
                            sC[(lr + 8) * CSTAGE_LD + nl]     = acc[mi][ni][2] + b0;
                            sC[(lr + 8) * CSTAGE_LD + nl + 1] = acc[mi][ni][3] + b1;
                        }
                    }
                }
                __syncthreads();
                const int grow0 = m0 + h * 32;
                #pragma unroll
                for (int i = 0; i < 16; i++) {
                    int e  = i * 256 + t;
                    int lr = e >> 7, c = e & 127;
                    int gc = n0 + c;
                    if (gc < nvalid)
                        ((float*)C)[(long long)(grow0 + lr) * ldc + gc] =
                            sC[lr * CSTAGE_LD + c];
                }
            }
            if (has_next) {
                CP_WAIT0();
                __syncthreads();
            }
        }
    }
}

// =====================================================================
// K3: attention, one block per (b,h); transposed Q/K layout +
// 4x4 register tiling -> conflict-free float4 smem traffic.
// =====================================================================
__global__ __launch_bounds__(256)
void attn_kernel(const __nv_bfloat16* __restrict__ qkv, const int* __restrict__ seq,
                 __nv_bfloat16* __restrict__ av)
{
    __shared__ float sqT[32][56];     // Q^T [d][s]
    __shared__ float skT[32][56];     // K^T [d][s]
    __shared__ float sv [SS][36];     // V   [s][d]
    __shared__ float sc [52][56];     // scores/probs [qi][kj]
    __shared__ int   spad[52];

    int b = blockIdx.x >> 2;
    int h = blockIdx.x & 3;
    int tid = threadIdx.x;

    for (int idx = tid; idx < SS * 4; idx += 256) {
        int s = idx >> 2, c = idx & 3;
        size_t base = ((size_t)(b * SS + s)) * 384 + h * 32 + c * 8;
        uint4 q4 = *reinterpret_cast<const uint4*>(qkv + base);
        uint4 k4 = *reinterpret_cast<const uint4*>(qkv + base + 128);
        uint4 v4 = *reinterpret_cast<const uint4*>(qkv + base + 256);
        const uint32_t* qw = (const uint32_t*)&q4;
        const uint32_t* kw = (const uint32_t*)&k4;
        const uint32_t* vw = (const uint32_t*)&v4;
        #pragma unroll
        for (int w = 0; w < 4; w++) {
            float2 qf = __bfloat1622float2(*(const __nv_bfloat162*)&qw[w]);
            float2 kf = __bfloat1622float2(*(const __nv_bfloat162*)&kw[w]);
            float2 vf = __bfloat1622float2(*(const __nv_bfloat162*)&vw[w]);
            int d = c * 8 + w * 2;
            sqT[d][s] = qf.x;  sqT[d + 1][s] = qf.y;
            skT[d][s] = kf.x;  skT[d + 1][s] = kf.y;
            sv[s][d]  = vf.x;  sv[s][d + 1]  = vf.y;
        }
    }
    if (tid < 52) spad[tid] = (tid < SS) ? (seq[b * SS + tid] == 0) : 1;
    __syncthreads();

    // ---- scores: 13x13 grid of 4x4 tiles (169 threads) ----
    if (tid < 169) {
        int qi0 = (tid / 13) * 4;
        int kj0 = (tid % 13) * 4;
        float acc[4][4];
        #pragma unroll
        for (int i = 0; i < 4; i++)
            #pragma unroll
            for (int jj = 0; jj < 4; jj++) acc[i][jj] = 0.f;
        #pragma unroll
        for (int d = 0; d < 32; d++) {
            float4 qv = *reinterpret_cast<const float4*>(&sqT[d][qi0]);
            float4 kv = *reinterpret_cast<const float4*>(&skT[d][kj0]);
            const float* qa = (const float*)&qv;
            const float* ka = (const float*)&kv;
            #pragma unroll
            for (int i = 0; i < 4; i++)
                #pragma unroll
                for (int jj = 0; jj < 4; jj++)
                    acc[i][jj] += qa[i] * ka[jj];
        }
        #pragma unroll
        for (int i = 0; i < 4; i++) {
            float4 row;
            float* ra = (float*)&row;
            #pragma unroll
            for (int jj = 0; jj < 4; jj++) {
                float v = acc[i][jj] * (1.0f / 32.0f);
                ra[jj] = (spad[qi0 + i] | spad[kj0 + jj]) ? NEGV : v;
            }
            *reinterpret_cast<float4*>(&sc[qi0 + i][kj0]) = row;
        }
    }
    __syncthreads();

    // ---- row softmax: one warp per row ----
    int wid = tid >> 5, lane = tid & 31;
    for (int r = wid; r < SS; r += 8) {
        float m = -INFINITY;
        for (int j = lane; j < SS; j += 32) m = fmaxf(m, sc[r][j]);
        #pragma unroll
        for (int o = 16; o; o >>= 1) m = fmaxf(m, __shfl_xor_sync(0xffffffffu, m, o));
        float sum = 0.f;
        for (int j = lane; j < SS; j += 32) {
            float e = expf(sc[r][j] - m);
            sc[r][j] = e;
            sum += e;
        }
        #pragma unroll
        for (int o = 16; o; o >>= 1) sum += __shfl_xor_sync(0xffffffffu, sum, o);
        float inv = 1.0f / sum;
        for (int j = lane; j < SS; j += 32) sc[r][j] *= inv;
    }
    __syncthreads();

    // ---- AV: 13x8 grid of 4(s)x4(d) tiles (104 threads) ----
    if (tid < 104) {
        int s0 = (tid / 8) * 4;
        int d0 = (tid % 8) * 4;
        float acc[4][4];
        #pragma unroll
        for (int i = 0; i < 4; i++)
            #pragma unroll
            for (int jj = 0; jj < 4; jj++) acc[i][jj] = 0.f;
        for (int j = 0; j < SS; j++) {
            float4 vv = *reinterpret_cast<const float4*>(&sv[j][d0]);
            const float* va = (const float*)&vv;
            #pragma unroll
            for (int i = 0; i < 4; i++) {
                float p = sc[s0 + i][j];
                #pragma unroll
                for (int jj = 0; jj < 4; jj++)
                    acc[i][jj] += p * va[jj];
            }
        }
        #pragma unroll
        for (int i = 0; i < 4; i++) {
            int s = s0 + i;
            if (s < SS) {
                size_t o = ((size_t)(b * SS + s)) * DD + h * 32 + d0;
                __nv_bfloat162 p0, p1;
                p0.x = __float2bfloat16(acc[i][0]); p0.y = __float2bfloat16(acc[i][1]);
                p1.x = __float2bfloat16(acc[i][2]); p1.y = __float2bfloat16(acc[i][3]);
                *reinterpret_cast<__nv_bfloat162*>(av + o)     = p0;
                *reinterpret_cast<__nv_bfloat162*>(av + o + 2) = p1;
            }
        }
    }
}

// =====================================================================
// K4: SelfEnc pooling, one block per batch; bf16 in, bf16 out
// =====================================================================
__global__ __launch_bounds__(128)
void pool_kernel(const __nv_bfloat16* __restrict__ enc, const float* __restrict__ w_enc,
                 const float* __restrict__ b_enc, __nv_bfloat16* __restrict__ p)
{
    __shared__ float se[SS][DD];
    __shared__ float swt[SS];
    __shared__ float swe[DD];
    int b = blockIdx.x;
    int tid = threadIdx.x;

    swe[tid] = w_enc[tid];
    for (int idx = tid; idx < SS * DD / 2; idx += 128) {
        __nv_bfloat162 v = *reinterpret_cast<const __nv_bfloat162*>(
            enc + (size_t)b * SS * DD + idx * 2);
        float2 f = __bfloat1622float2(v);
        int r = (idx * 2) >> 7, c = (idx * 2) & 127;
        se[r][c] = f.x;
        se[r][c + 1] = f.y;
    }
    __syncthreads();

    int wid = tid >> 5, lane = tid & 31;
    for (int s = wid; s < SS; s += 4) {
        float acc = 0.f;
        #pragma unroll
        for (int d = lane; d < DD; d += 32) acc += se[s][d] * swe[d];
        #pragma unroll
        for (int o = 16; o; o >>= 1) acc += __shfl_xor_sync(0xffffffffu, acc, o);
        if (lane == 0) swt[s] = acc + b_enc[0];
    }
    __syncthreads();

    float acc = 0.f;
    #pragma unroll
    for (int s = 0; s < SS; s++) acc += swt[s] * se[s][tid];
    p[b * DD + tid] = __float2bfloat16(acc);
}

// =====================================================================
// K5: consumed-item mask scatter
// =====================================================================
__global__ void mask_kernel(const int* __restrict__ seq, float* __restrict__ out)
{
    int b = blockIdx.x;
    int s = threadIdx.x;
    if (s < SS) out[(size_t)b * VV + seq[b * SS + s]] = NEGV;
}

// =====================================================================
// launch
// =====================================================================
extern "C" void kernel_launch(void* const* d_in, const int* in_sizes, int n_in,
                              void* d_out, int out_size)
{
    const int*   seq    = (const int*)  d_in[0];
    const int*   subty  = (const int*)  d_in[1];
    const float* emb    = (const float*)d_in[2];
    const float* sgt    = (const float*)d_in[3];
    const float* wq     = (const float*)d_in[4];
    const float* bq     = (const float*)d_in[5];
    const float* wk     = (const float*)d_in[6];
    const float* bk     = (const float*)d_in[7];
    const float* wv     = (const float*)d_in[8];
    const float* bv     = (const float*)d_in[9];
    const float* wo     = (const float*)d_in[10];
    const float* bo     = (const float*)d_in[11];
    const float* w_enc  = (const float*)d_in[12];
    const float* b_enc  = (const float*)d_in[13];
    const float* wscore = (const float*)d_in[14];
    const float* bscore = (const float*)d_in[15];
    float* out = (float*)d_out;

    __nv_bfloat16 *x, *qkv, *av, *enc, *p, *ws, *w4;
    float *b3;
    cudaGetSymbolAddress((void**)&x,    g_x);
    cudaGetSymbolAddress((void**)&qkv,  g_qkv);
    cudaGetSymbolAddress((void**)&av,   g_av);
    cudaGetSymbolAddress((void**)&enc,  g_enc);
    cudaGetSymbolAddress((void**)&p,    g_p);
    cudaGetSymbolAddress((void**)&ws,   g_ws);
    cudaGetSymbolAddress((void**)&w4,   g_w4);
    cudaGetSymbolAddress((void**)&b3,   g_b3);

    const int GEMM_SMEM = TILE_B_SMEM + 2 * TILE_A_SMEM + 512;   // 70144
    cudaFuncSetAttribute((const void*)mma_gemm<__nv_bfloat16>,
                         cudaFuncAttributeMaxDynamicSharedMemorySize, GEMM_SMEM);
    cudaFuncSetAttribute((const void*)mma_gemm<float>,
                         cudaFuncAttributeMaxDynamicSharedMemorySize, GEMM_SMEM);

    // 1) merged prep: embed+PE, weight transposes, bias concat
    prep_kernel<<<PREP_EMBED + PREP_WSV + 16 + 1, 128>>>(
        seq, subty, emb, sgt, wscore, wq, wk, wv, wo, bq, bk, bv,
        x, ws, w4, b3);

    // 2) fused QKV projection (bf16 out): grid (3, 98) x m_iters 8
    mma_gemm<__nv_bfloat16><<<dim3(3, BS / 64 / 8), 256, GEMM_SMEM>>>(
        x, w4, b3, qkv, 384, 384, 8);

    // 3) attention (bf16 in/out, register-tiled)
    attn_kernel<<<BB * HH, 256>>>(qkv, seq, av);

    // 4) output projection (bf16 out): grid (1, 98) x m_iters 8
    mma_gemm<__nv_bfloat16><<<dim3(1, BS / 64 / 8), 256, GEMM_SMEM>>>(
        av, w4 + 3 * DD * DD, bo, enc, DD, DD, 8);

    // 5) pooling (bf16 in, bf16 out)
    pool_kernel<<<BB, 128>>>(enc, w_enc, b_enc, p);

    // 6) novelty scores: grid (782, 1) x m_iters 16 = 16 M-tiles (FULL coverage)
    mma_gemm<float><<<dim3(VV_PAD / 128, 1), 256, GEMM_SMEM>>>(
        p, ws, bscore, out, (long long)VV, VV, 16);

    // 7) consumed mask
    mask_kernel<<<BB, 64>>>(seq, out);
}

// round 16
// speedup vs baseline: 1.0202x; 1.0202x over previous
#include <cuda_runtime.h>
#include <cuda_bf16.h>
#include <math.h>
#include <stdint.h>

// Problem constants
#define BB   1024
#define SS   49
#define DD   128
#define HH   4
#define VV   100001
#define VV_PAD 100096            // 782 * 128
#define BS   (BB*SS)             // 50176
#define NEGV (-1e8f)

typedef unsigned long long ull;

// =====================================================================
// scratch (device globals: no allocs allowed)
// =====================================================================
__device__ __align__(256) __nv_bfloat16 g_x   [BS * DD];              // embedded bf16
__device__ __align__(256) __nv_bfloat16 g_qkv [BS * 3 * DD];          // q|k|v concat bf16, ld=384
__device__ __align__(256) __nv_bfloat16 g_av  [BS * DD];              // attention out, bf16
__device__ __align__(256) __nv_bfloat16 g_enc [BS * DD];              // encoder out, bf16
__device__ __align__(256) __nv_bfloat16 g_p   [BB * DD];              // pooled, bf16
__device__ __align__(256) __nv_bfloat16 g_ws  [(size_t)VV_PAD * DD];  // w_score^T [n][k] bf16
__device__ __align__(256) __nv_bfloat16 g_w4  [4][DD * DD];           // wq,wk,wv,wo ^T bf16
__device__ __align__(256) float         g_b3  [3 * DD];               // bq|bk|bv concat

// =====================================================================
// PTX helpers
// =====================================================================
__device__ __forceinline__ void mma_bf16(float* c, const uint32_t* a, const uint32_t* b) {
    asm volatile(
        "mma.sync.aligned.m16n8k16.row.col.f32.bf16.bf16.f32 "
        "{%0,%1,%2,%3}, {%4,%5,%6,%7}, {%8,%9}, {%0,%1,%2,%3};"
        : "+f"(c[0]), "+f"(c[1]), "+f"(c[2]), "+f"(c[3])
        : "r"(a[0]), "r"(a[1]), "r"(a[2]), "r"(a[3]), "r"(b[0]), "r"(b[1]));
}
__device__ __forceinline__ uint32_t cvta_smem(const void* p) {
    uint32_t a;
    asm("{ .reg .u64 t; cvta.to.shared.u64 t, %1; cvt.u32.u64 %0, t; }"
        : "=r"(a) : "l"(p));
    return a;
}
__device__ __forceinline__ void ldsm_x4(uint32_t* r, uint32_t addr) {
    asm volatile("ldmatrix.sync.aligned.m8n8.x4.shared.b16 {%0,%1,%2,%3}, [%4];"
                 : "=r"(r[0]), "=r"(r[1]), "=r"(r[2]), "=r"(r[3]) : "r"(addr));
}
__device__ __forceinline__ void cp16(uint32_t s, const void* g) {
    asm volatile("cp.async.ca.shared.global [%0], [%1], 16;" :: "r"(s), "l"(g));
}
#define CP_COMMIT() asm volatile("cp.async.commit_group;" ::: "memory")
#define CP_WAIT0()  asm volatile("cp.async.wait_group 0;" ::: "memory")

// smem tile geometry: rows x 128 bf16, padded row stride = 272 bytes
#define ROWB 272
#define TILE_A_SMEM (64 * ROWB)    // 17408
#define TILE_B_SMEM (128 * ROWB)   // 34816
#define CSTAGE_LD   132            // fp32 staging row stride (words)

// =====================================================================
// K1 (merged prep): embed+PE | w_score transpose | w4 transpose | bias3
// =====================================================================
#define PREP_EMBED  BS                     // 50176
#define PREP_WSV    (VV_PAD / 32)          // 3128
__global__ __launch_bounds__(128)
void prep_kernel(const int* __restrict__ seq, const int* __restrict__ sub,
                 const float* __restrict__ emb, const float* __restrict__ sgt,
                 const float* __restrict__ wscore,
                 const float* __restrict__ w0, const float* __restrict__ w1,
                 const float* __restrict__ w2, const float* __restrict__ w3,
                 const float* __restrict__ bq, const float* __restrict__ bk,
                 const float* __restrict__ bv,
                 __nv_bfloat16* __restrict__ x, __nv_bfloat16* __restrict__ ws,
                 __nv_bfloat16* __restrict__ w4, float* __restrict__ b3)
{
    __shared__ float st[32][129];
    const int bid = blockIdx.x;
    const int t = threadIdx.x;

    if (bid < PREP_EMBED) {
        int bs = bid;
        int s  = bs % SS;
        int item = seq[bs];
        int stype = sub[bs];
        float pe = (t & 1) ? cosf((float)s) : sinf((float)s);
        float v  = emb[(size_t)item * DD + t] + sgt[(size_t)stype * DD + t] + pe;
        x[(size_t)bs * DD + t] = __float2bfloat16(v);
        return;
    }
    if (bid < PREP_EMBED + PREP_WSV) {
        int n0 = (bid - PREP_EMBED) * 32;
        #pragma unroll
        for (int rep = 0; rep < 32; rep++) {
            int i = rep * 128 + t;
            int k = i >> 5, j = i & 31;
            int n = n0 + j;
            st[j][k] = (n < VV) ? wscore[(size_t)k * VV + n] : 0.f;
        }
        __syncthreads();
        #pragma unroll
        for (int rep = 0; rep < 32; rep++) {
            int i = rep * 128 + t;
            int nl = i >> 7, k = i & 127;
            ws[(size_t)(n0 + nl) * DD + k] = __float2bfloat16(st[nl][k]);
        }
        return;
    }
    if (bid < PREP_EMBED + PREP_WSV + 16) {
        int r  = bid - PREP_EMBED - PREP_WSV;
        int w  = r >> 2;
        int n0 = (r & 3) * 32;
        const float* W = (w == 0) ? w0 : (w == 1) ? w1 : (w == 2) ? w2 : w3;
        __nv_bfloat16* T = w4 + (size_t)w * DD * DD;
        #pragma unroll
        for (int rep = 0; rep < 32; rep++) {
            int i = rep * 128 + t;
            int k = i >> 5, j = i & 31;
            st[j][k] = W[(size_t)k * DD + n0 + j];
        }
        __syncthreads();
        #pragma unroll
        for (int rep = 0; rep < 32; rep++) {
            int i = rep * 128 + t;
            int nl = i >> 7, k = i & 127;
            T[(size_t)(n0 + nl) * DD + k] = __float2bfloat16(st[nl][k]);
        }
        return;
    }
    for (int i = t; i < 384; i += 128)
        b3[i] = (i < 128) ? bq[i] : (i < 256) ? bk[i - 128] : bv[i - 256];
}

// =====================================================================
// K2: bf16 tensor-core GEMM (warp tile 32x32, CTA 64x128).
// bf16 output: double-buffered A + direct bf16x2 stores.
// fp32 output: single A buffer, next-A cp.async issued BEFORE the staged
//   epilogue (load hides under the 32KB coalesced store phase).
// =====================================================================
template<typename OutT>
__global__ __launch_bounds__(256, 3)
void mma_gemm(const __nv_bfloat16* __restrict__ A, const __nv_bfloat16* __restrict__ B,
              const float* __restrict__ bias, OutT* __restrict__ C,
              long long ldc, int nvalid, int m_iters)
{
    extern __shared__ char sm[];
    char* sB    = sm;
    char* sAbuf = sB + TILE_B_SMEM;                 // 2 x TILE_A_SMEM region
    float* sbias = (float*)(sAbuf + 2 * TILE_A_SMEM);
    float* sC    = (float*)(sAbuf + TILE_A_SMEM);   // fp32 path: 32x132 staging

    const int t = threadIdx.x;
    const int lane = t & 31;
    const int wid  = t >> 5;
    const int warp_m = wid >> 2;        // 0..1 (32 rows each)
    const int warp_n = wid & 3;         // 0..3 (32 cols each)
    const int n0 = blockIdx.x * 128;

    const uint32_t sBu = cvta_smem(sB);
    const uint32_t sAu = cvta_smem(sAbuf);

    // ---- async load B tile + first A tile ----
    {
        const __nv_bfloat16* gB = B + (size_t)n0 * DD;
        #pragma unroll
        for (int i = 0; i < 8; i++) {
            int idx = i * 256 + t;
            int r = idx >> 4, seg = idx & 15;
            cp16(sBu + r * ROWB + seg * 16, gB + (size_t)r * DD + seg * 8);
        }
        const __nv_bfloat16* gA = A + (size_t)(blockIdx.y * m_iters) * 64 * DD;
        #pragma unroll
        for (int i = 0; i < 4; i++) {
            int idx = i * 256 + t;
            int r = idx >> 4, seg = idx & 15;
            cp16(sAu + r * ROWB + seg * 16, gA + (size_t)r * DD + seg * 8);
        }
        CP_COMMIT();
        if (t < 128) sbias[t] = (n0 + t < nvalid) ? bias[n0 + t] : 0.f;
        CP_WAIT0();
    }
    __syncthreads();

    // ---- ldmatrix lane addressing ----
    const int quad = lane >> 3, j = lane & 7;
    const uint32_t aLane = (uint32_t)((warp_m * 32 + (quad & 1) * 8 + j) * ROWB
                                      + (quad >> 1) * 16);
    const uint32_t bLane = sBu
                         + (uint32_t)((warp_n * 32 + (quad >> 1) * 8 + j) * ROWB
                                      + (quad & 1) * 16);

    const int frow = lane >> 2;
    int cur = 0;

    for (int iter = 0; iter < m_iters; iter++) {
        const int m0 = (blockIdx.y * m_iters + iter) * 64;
        const bool has_next = (iter + 1 < m_iters);

        if constexpr (sizeof(OutT) == 2) {
            if (has_next) {
                const __nv_bfloat16* gn = A + (size_t)(m0 + 64) * DD;
                const uint32_t dst = sAu + (uint32_t)((cur ^ 1) * TILE_A_SMEM);
                #pragma unroll
                for (int i = 0; i < 4; i++) {
                    int idx = i * 256 + t;
                    int r = idx >> 4, seg = idx & 15;
                    cp16(dst + r * ROWB + seg * 16, gn + (size_t)r * DD + seg * 8);
                }
                CP_COMMIT();
            }
        }

        const uint32_t aAddr = aLane + sAu + (uint32_t)(cur * TILE_A_SMEM);

        float acc[2][4][4];
        #pragma unroll
        for (int mi = 0; mi < 2; mi++)
            #pragma unroll
            for (int ni = 0; ni < 4; ni++)
                #pragma unroll
                for (int e = 0; e < 4; e++) acc[mi][ni][e] = 0.f;

        #pragma unroll
        for (int kb = 0; kb < 8; kb++) {
            const uint32_t ko = kb * 32;
            uint32_t a0[4], a1[4], b01[4], b23[4];
            ldsm_x4(a0,  aAddr + ko);
            ldsm_x4(a1,  aAddr + ko + 16 * ROWB);
            ldsm_x4(b01, bLane + ko);
            ldsm_x4(b23, bLane + ko + 16 * ROWB);
            mma_bf16(acc[0][0], a0, b01);  mma_bf16(acc[0][1], a0, b01 + 2);
            mma_bf16(acc[0][2], a0, b23);  mma_bf16(acc[0][3], a0, b23 + 2);
            mma_bf16(acc[1][0], a1, b01);  mma_bf16(acc[1][1], a1, b01 + 2);
            mma_bf16(acc[1][2], a1, b23);  mma_bf16(acc[1][3], a1, b23 + 2);
        }

        if constexpr (sizeof(OutT) == 2) {
            #pragma unroll
            for (int mi = 0; mi < 2; mi++) {
                const int r0 = m0 + warp_m * 32 + mi * 16 + frow;
                OutT* crow0 = C + (long long)r0 * ldc;
                OutT* crow1 = C + (long long)(r0 + 8) * ldc;
                #pragma unroll
                for (int ni = 0; ni < 4; ni++) {
                    const int nl = warp_n * 32 + ni * 8 + (lane & 3) * 2;
                    const int n  = n0 + nl;
                    const float b0 = sbias[nl], b1 = sbias[nl + 1];
                    __nv_bfloat162 s0, s1;
                    s0.x = __float2bfloat16(acc[mi][ni][0] + b0);
                    s0.y = __float2bfloat16(acc[mi][ni][1] + b1);
                    s1.x = __float2bfloat16(acc[mi][ni][2] + b0);
                    s1.y = __float2bfloat16(acc[mi][ni][3] + b1);
                    *reinterpret_cast<__nv_bfloat162*>(crow0 + n) = s0;
                    *reinterpret_cast<__nv_bfloat162*>(crow1 + n) = s1;
                }
            }
            if (has_next) {
                CP_WAIT0();
                __syncthreads();
                cur ^= 1;
            }
        } else {
            // ---- issue next-A load NOW (hides under epilogue stores) ----
            if (has_next) {
                __syncthreads();   // all ldmatrix reads of sA complete
                const __nv_bfloat16* gn = A + (size_t)(m0 + 64) * DD;
                #pragma unroll
                for (int i = 0; i < 4; i++) {
                    int idx = i * 256 + t;
                    int r = idx >> 4, seg = idx & 15;
                    cp16(sAu + r * ROWB + seg * 16, gn + (size_t)r * DD + seg * 8);
                }
                CP_COMMIT();
            }
            // ---- fp32 epilogue: smem-staged (float2), coalesced stores ----
            #pragma unroll
            for (int h = 0; h < 2; h++) {
                __syncthreads();
                if (warp_m == h) {
                    #pragma unroll
                    for (int mi = 0; mi < 2; mi++) {
                        const int lr = mi * 16 + frow;
                        #pragma unroll
                        for (int ni = 0; ni < 4; ni++) {
                            const int nl = warp_n * 32 + ni * 8 + (lane & 3) * 2;
                            const float b0 = sbias[nl], b1 = sbias[nl + 1];
                            *reinterpret_cast<float2*>(&sC[lr * CSTAGE_LD + nl]) =
                                make_float2(acc[mi][ni][0] + b0, acc[mi][ni][1] + b1);
                            *reinterpret_cast<float2*>(&sC[(lr + 8) * CSTAGE_LD + nl]) =
                                make_float2(acc[mi][ni][2] + b0, acc[mi][ni][3] + b1);
                        }
                    }
                }
                __syncthreads();
                const int grow0 = m0 + h * 32;
                #pragma unroll
                for (int i = 0; i < 16; i++) {
                    int e  = i * 256 + t;
                    int lr = e >> 7, c = e & 127;
                    int gc = n0 + c;
                    if (gc < nvalid)
                        ((float*)C)[(long long)(grow0 + lr) * ldc + gc] =
                            sC[lr * CSTAGE_LD + c];
                }
            }
            if (has_next) {
                CP_WAIT0();
                __syncthreads();
            }
        }
    }
}

// =====================================================================
// K3: attention, one block per (b,h); transposed Q/K layout +
// 4x4 register tiling -> conflict-free float4 smem traffic.
// =====================================================================
__global__ __launch_bounds__(256)
void attn_kernel(const __nv_bfloat16* __restrict__ qkv, const int* __restrict__ seq,
                 __nv_bfloat16* __restrict__ av)
{
    __shared__ float sqT[32][56];     // Q^T [d][s]
    __shared__ float skT[32][56];     // K^T [d][s]
    __shared__ float sv [SS][36];     // V   [s][d]
    __shared__ float sc [52][56];     // scores/probs [qi][kj]
    __shared__ int   spad[52];

    int b = blockIdx.x >> 2;
    int h = blockIdx.x & 3;
    int tid = threadIdx.x;

    for (int idx = tid; idx < SS * 4; idx += 256) {
        int s = idx >> 2, c = idx & 3;
        size_t base = ((size_t)(b * SS + s)) * 384 + h * 32 + c * 8;
        uint4 q4 = *reinterpret_cast<const uint4*>(qkv + base);
        uint4 k4 = *reinterpret_cast<const uint4*>(qkv + base + 128);
        uint4 v4 = *reinterpret_cast<const uint4*>(qkv + base + 256);
        const uint32_t* qw = (const uint32_t*)&q4;
        const uint32_t* kw = (const uint32_t*)&k4;
        const uint32_t* vw = (const uint32_t*)&v4;
        #pragma unroll
        for (int w = 0; w < 4; w++) {
            float2 qf = __bfloat1622float2(*(const __nv_bfloat162*)&qw[w]);
            float2 kf = __bfloat1622float2(*(const __nv_bfloat162*)&kw[w]);
            float2 vf = __bfloat1622float2(*(const __nv_bfloat162*)&vw[w]);
            int d = c * 8 + w * 2;
            sqT[d][s] = qf.x;  sqT[d + 1][s] = qf.y;
            skT[d][s] = kf.x;  skT[d + 1][s] = kf.y;
            sv[s][d]  = vf.x;  sv[s][d + 1]  = vf.y;
        }
    }
    if (tid < 52) spad[tid] = (tid < SS) ? (seq[b * SS + tid] == 0) : 1;
    __syncthreads();

    // ---- scores: 13x13 grid of 4x4 tiles (169 threads) ----
    if (tid < 169) {
        int qi0 = (tid / 13) * 4;
        int kj0 = (tid % 13) * 4;
        float acc[4][4];
        #pragma unroll
        for (int i = 0; i < 4; i++)
            #pragma unroll
            for (int jj = 0; jj < 4; jj++) acc[i][jj] = 0.f;
        #pragma unroll
        for (int d = 0; d < 32; d++) {
            float4 qv = *reinterpret_cast<const float4*>(&sqT[d][qi0]);
            float4 kv = *reinterpret_cast<const float4*>(&skT[d][kj0]);
            const float* qa = (const float*)&qv;
            const float* ka = (const float*)&kv;
            #pragma unroll
            for (int i = 0; i < 4; i++)
                #pragma unroll
                for (int jj = 0; jj < 4; jj++)
                    acc[i][jj] += qa[i] * ka[jj];
        }
        #pragma unroll
        for (int i = 0; i < 4; i++) {
            float4 row;
            float* ra = (float*)&row;
            #pragma unroll
            for (int jj = 0; jj < 4; jj++) {
                float v = acc[i][jj] * (1.0f / 32.0f);
                ra[jj] = (spad[qi0 + i] | spad[kj0 + jj]) ? NEGV : v;
            }
            *reinterpret_cast<float4*>(&sc[qi0 + i][kj0]) = row;
        }
    }
    __syncthreads();

    // ---- row softmax: one warp per row ----
    int wid = tid >> 5, lane = tid & 31;
    for (int r = wid; r < SS; r += 8) {
        float m = -INFINITY;
        for (int j = lane; j < SS; j += 32) m = fmaxf(m, sc[r][j]);
        #pragma unroll
        for (int o = 16; o; o >>= 1) m = fmaxf(m, __shfl_xor_sync(0xffffffffu, m, o));
        float sum = 0.f;
        for (int j = lane; j < SS; j += 32) {
            float e = expf(sc[r][j] - m);
            sc[r][j] = e;
            sum += e;
        }
        #pragma unroll
        for (int o = 16; o; o >>= 1) sum += __shfl_xor_sync(0xffffffffu, sum, o);
        float inv = 1.0f / sum;
        for (int j = lane; j < SS; j += 32) sc[r][j] *= inv;
    }
    __syncthreads();

    // ---- AV: 13x8 grid of 4(s)x4(d) tiles (104 threads) ----
    if (tid < 104) {
        int s0 = (tid / 8) * 4;
        int d0 = (tid % 8) * 4;
        float acc[4][4];
        #pragma unroll
        for (int i = 0; i < 4; i++)
            #pragma unroll
            for (int jj = 0; jj < 4; jj++) acc[i][jj] = 0.f;
        for (int j = 0; j < SS; j++) {
            float4 vv = *reinterpret_cast<const float4*>(&sv[j][d0]);
            const float* va = (const float*)&vv;
            #pragma unroll
            for (int i = 0; i < 4; i++) {
                float p = sc[s0 + i][j];
                #pragma unroll
                for (int jj = 0; jj < 4; jj++)
                    acc[i][jj] += p * va[jj];
            }
        }
        #pragma unroll
        for (int i = 0; i < 4; i++) {
            int s = s0 + i;
            if (s < SS) {
                size_t o = ((size_t)(b * SS + s)) * DD + h * 32 + d0;
                __nv_bfloat162 p0, p1;
                p0.x = __float2bfloat16(acc[i][0]); p0.y = __float2bfloat16(acc[i][1]);
                p1.x = __float2bfloat16(acc[i][2]); p1.y = __float2bfloat16(acc[i][3]);
                *reinterpret_cast<__nv_bfloat162*>(av + o)     = p0;
                *reinterpret_cast<__nv_bfloat162*>(av + o + 2) = p1;
            }
        }
    }
}

// =====================================================================
// K4: SelfEnc pooling, one block per batch; bf16 in, bf16 out
// =====================================================================
__global__ __launch_bounds__(128)
void pool_kernel(const __nv_bfloat16* __restrict__ enc, const float* __restrict__ w_enc,
                 const float* __restrict__ b_enc, __nv_bfloat16* __restrict__ p)
{
    __shared__ float se[SS][DD];
    __shared__ float swt[SS];
    __shared__ float swe[DD];
    int b = blockIdx.x;
    int tid = threadIdx.x;

    swe[tid] = w_enc[tid];
    for (int idx = tid; idx < SS * DD / 2; idx += 128) {
        __nv_bfloat162 v = *reinterpret_cast<const __nv_bfloat162*>(
            enc + (size_t)b * SS * DD + idx * 2);
        float2 f = __bfloat1622float2(v);
        int r = (idx * 2) >> 7, c = (idx * 2) & 127;
        se[r][c] = f.x;
        se[r][c + 1] = f.y;
    }
    __syncthreads();

    int wid = tid >> 5, lane = tid & 31;
    for (int s = wid; s < SS; s += 4) {
        float acc = 0.f;
        #pragma unroll
        for (int d = lane; d < DD; d += 32) acc += se[s][d] * swe[d];
        #pragma unroll
        for (int o = 16; o; o >>= 1) acc += __shfl_xor_sync(0xffffffffu, acc, o);
        if (lane == 0) swt[s] = acc + b_enc[0];
    }
    __syncthreads();

    float acc = 0.f;
    #pragma unroll
    for (int s = 0; s < SS; s++) acc += swt[s] * se[s][tid];
    p[b * DD + tid] = __float2bfloat16(acc);
}

// =====================================================================
// K5: consumed-item mask scatter
// =====================================================================
__global__ void mask_kernel(const int* __restrict__ seq, float* __restrict__ out)
{
    int b = blockIdx.x;
    int s = threadIdx.x;
    if (s < SS) out[(size_t)b * VV + seq[b * SS + s]] = NEGV;
}

// =====================================================================
// launch
// =====================================================================
extern "C" void kernel_launch(void* const* d_in, const int* in_sizes, int n_in,
                              void* d_out, int out_size)
{
    const int*   seq    = (const int*)  d_in[0];
    const int*   subty  = (const int*)  d_in[1];
    const float* emb    = (const float*)d_in[2];
    const float* sgt    = (const float*)d_in[3];
    const float* wq     = (const float*)d_in[4];
    const float* bq     = (const float*)d_in[5];
    const float* wk     = (const float*)d_in[6];
    const float* bk     = (const float*)d_in[7];
    const float* wv     = (const float*)d_in[8];
    const float* bv     = (const float*)d_in[9];
    const float* wo     = (const float*)d_in[10];
    const float* bo     = (const float*)d_in[11];
    const float* w_enc  = (const float*)d_in[12];
    const float* b_enc  = (const float*)d_in[13];
    const float* wscore = (const float*)d_in[14];
    const float* bscore = (const float*)d_in[15];
    float* out = (float*)d_out;

    __nv_bfloat16 *x, *qkv, *av, *enc, *p, *ws, *w4;
    float *b3;
    cudaGetSymbolAddress((void**)&x,    g_x);
    cudaGetSymbolAddress((void**)&qkv,  g_qkv);
    cudaGetSymbolAddress((void**)&av,   g_av);
    cudaGetSymbolAddress((void**)&enc,  g_enc);
    cudaGetSymbolAddress((void**)&p,    g_p);
    cudaGetSymbolAddress((void**)&ws,   g_ws);
    cudaGetSymbolAddress((void**)&w4,   g_w4);
    cudaGetSymbolAddress((void**)&b3,   g_b3);

    const int GEMM_SMEM = TILE_B_SMEM + 2 * TILE_A_SMEM + 512;   // 70144
    cudaFuncSetAttribute((const void*)mma_gemm<__nv_bfloat16>,
                         cudaFuncAttributeMaxDynamicSharedMemorySize, GEMM_SMEM);
    cudaFuncSetAttribute((const void*)mma_gemm<float>,
                         cudaFuncAttributeMaxDynamicSharedMemorySize, GEMM_SMEM);

    // 1) merged prep: embed+PE, weight transposes, bias concat
    prep_kernel<<<PREP_EMBED + PREP_WSV + 16 + 1, 128>>>(
        seq, subty, emb, sgt, wscore, wq, wk, wv, wo, bq, bk, bv,
        x, ws, w4, b3);

    // 2) fused QKV projection (bf16 out): grid (3, 98) x m_iters 8
    mma_gemm<__nv_bfloat16><<<dim3(3, BS / 64 / 8), 256, GEMM_SMEM>>>(
        x, w4, b3, qkv, 384, 384, 8);

    // 3) attention (bf16 in/out, register-tiled)
    attn_kernel<<<BB * HH, 256>>>(qkv, seq, av);

    // 4) output projection (bf16 out): grid (1, 98) x m_iters 8
    mma_gemm<__nv_bfloat16><<<dim3(1, BS / 64 / 8), 256, GEMM_SMEM>>>(
        av, w4 + 3 * DD * DD, bo, enc, DD, DD, 8);

    // 5) pooling (bf16 in, bf16 out)
    pool_kernel<<<BB, 128>>>(enc, w_enc, b_enc, p);

    // 6) novelty scores: grid (782, 2) x m_iters 8 = 16 M-tiles (FULL coverage)
    mma_gemm<float><<<dim3(VV_PAD / 128, 2), 256, GEMM_SMEM>>>(
        p, ws, bscore, out, (long long)VV, VV, 8);

    // 7) consumed mask
    mask_kernel<<<BB, 64>>>(seq, out);
}

// round 17
// speedup vs baseline: 1.0204x; 1.0002x over previous
#include <cuda_runtime.h>
#include <cuda_bf16.h>
#include <math.h>
#include <stdint.h>

// Problem constants
#define BB   1024
#define SS   49
#define DD   128
#define HH   4
#define VV   100001
#define VV_PAD 100096            // 782 * 128
#define BS   (BB*SS)             // 50176
#define NEGV (-1e8f)

typedef unsigned long long ull;

// =====================================================================
// scratch (device globals: no allocs allowed)
// =====================================================================
__device__ __align__(256) __nv_bfloat16 g_x   [BS * DD];              // embedded bf16
__device__ __align__(256) __nv_bfloat16 g_qkv [BS * 3 * DD];          // q|k|v concat bf16, ld=384
__device__ __align__(256) __nv_bfloat16 g_av  [BS * DD];              // attention out, bf16
__device__ __align__(256) __nv_bfloat16 g_enc [BS * DD];              // encoder out, bf16
__device__ __align__(256) __nv_bfloat16 g_p   [BB * DD];              // pooled, bf16
__device__ __align__(256) __nv_bfloat16 g_ws  [(size_t)VV_PAD * DD];  // w_score^T [n][k] bf16
__device__ __align__(256) __nv_bfloat16 g_w4  [4][DD * DD];           // wq,wk,wv,wo ^T bf16
__device__ __align__(256) float         g_b3  [3 * DD];               // bq|bk|bv concat

// =====================================================================
// PTX helpers
// =====================================================================
__device__ __forceinline__ void mma_bf16(float* c, const uint32_t* a, const uint32_t* b) {
    asm volatile(
        "mma.sync.aligned.m16n8k16.row.col.f32.bf16.bf16.f32 "
        "{%0,%1,%2,%3}, {%4,%5,%6,%7}, {%8,%9}, {%0,%1,%2,%3};"
        : "+f"(c[0]), "+f"(c[1]), "+f"(c[2]), "+f"(c[3])
        : "r"(a[0]), "r"(a[1]), "r"(a[2]), "r"(a[3]), "r"(b[0]), "r"(b[1]));
}
__device__ __forceinline__ uint32_t cvta_smem(const void* p) {
    uint32_t a;
    asm("{ .reg .u64 t; cvta.to.shared.u64 t, %1; cvt.u32.u64 %0, t; }"
        : "=r"(a) : "l"(p));
    return a;
}
__device__ __forceinline__ void ldsm_x4(uint32_t* r, uint32_t addr) {
    asm volatile("ldmatrix.sync.aligned.m8n8.x4.shared.b16 {%0,%1,%2,%3}, [%4];"
                 : "=r"(r[0]), "=r"(r[1]), "=r"(r[2]), "=r"(r[3]) : "r"(addr));
}
__device__ __forceinline__ void cp16(uint32_t s, const void* g) {
    asm volatile("cp.async.ca.shared.global [%0], [%1], 16;" :: "r"(s), "l"(g));
}
#define CP_COMMIT() asm volatile("cp.async.commit_group;" ::: "memory")
#define CP_WAIT0()  asm volatile("cp.async.wait_group 0;" ::: "memory")

// FMA-only exp for x <= 0 (avoids MUFU.EX2; MUFU is the attention bottleneck:
// 9.8M exps at 0.5/cyc/SM = 76us chip floor, vs ~2us on the FMA pipe).
// exp(x) = 2^(x*log2e); split y = fl + f, f in [0,1); degree-5 Taylor of 2^f
// (max rel err ~1.5e-4, far inside tolerance); scale by 2^fl via exponent bits.
__device__ __forceinline__ float fexp(float x) {
    float y = x * 1.44269504f;
    y = fmaxf(y, -126.0f);
    float fl = floorf(y);
    float f  = y - fl;
    float p = 1.3333558e-3f;
    p = fmaf(p, f, 9.6181291e-3f);
    p = fmaf(p, f, 5.5504109e-2f);
    p = fmaf(p, f, 2.4022651e-1f);
    p = fmaf(p, f, 6.9314718e-1f);
    p = fmaf(p, f, 1.0f);
    float s = __int_as_float(((int)fl + 127) << 23);
    return p * s;
}

// smem tile geometry: rows x 128 bf16, padded row stride = 272 bytes
#define ROWB 272
#define TILE_A_SMEM (64 * ROWB)    // 17408
#define TILE_B_SMEM (128 * ROWB)   // 34816
#define CSTAGE_LD   132            // fp32 staging row stride (words)

// =====================================================================
// K1 (merged prep): embed+PE | w_score transpose | w4 transpose | bias3
// =====================================================================
#define PREP_EMBED  BS                     // 50176
#define PREP_WSV    (VV_PAD / 32)          // 3128
__global__ __launch_bounds__(128)
void prep_kernel(const int* __restrict__ seq, const int* __restrict__ sub,
                 const float* __restrict__ emb, const float* __restrict__ sgt,
                 const float* __restrict__ wscore,
                 const float* __restrict__ w0, const float* __restrict__ w1,
                 const float* __restrict__ w2, const float* __restrict__ w3,
                 const float* __restrict__ bq, const float* __restrict__ bk,
                 const float* __restrict__ bv,
                 __nv_bfloat16* __restrict__ x, __nv_bfloat16* __restrict__ ws,
                 __nv_bfloat16* __restrict__ w4, float* __restrict__ b3)
{
    __shared__ float st[32][129];
    const int bid = blockIdx.x;
    const int t = threadIdx.x;

    if (bid < PREP_EMBED) {
        int bs = bid;
        int s  = bs % SS;
        int item = seq[bs];
        int stype = sub[bs];
        float pe = (t & 1) ? cosf((float)s) : sinf((float)s);
        float v  = emb[(size_t)item * DD + t] + sgt[(size_t)stype * DD + t] + pe;
        x[(size_t)bs * DD + t] = __float2bfloat16(v);
        return;
    }
    if (bid < PREP_EMBED + PREP_WSV) {
        int n0 = (bid - PREP_EMBED) * 32;
        #pragma unroll
        for (int rep = 0; rep < 32; rep++) {
            int i = rep * 128 + t;
            int k = i >> 5, j = i & 31;
            int n = n0 + j;
            st[j][k] = (n < VV) ? wscore[(size_t)k * VV + n] : 0.f;
        }
        __syncthreads();
        #pragma unroll
        for (int rep = 0; rep < 32; rep++) {
            int i = rep * 128 + t;
            int nl = i >> 7, k = i & 127;
            ws[(size_t)(n0 + nl) * DD + k] = __float2bfloat16(st[nl][k]);
        }
        return;
    }
    if (bid < PREP_EMBED + PREP_WSV + 16) {
        int r  = bid - PREP_EMBED - PREP_WSV;
        int w  = r >> 2;
        int n0 = (r & 3) * 32;
        const float* W = (w == 0) ? w0 : (w == 1) ? w1 : (w == 2) ? w2 : w3;
        __nv_bfloat16* T = w4 + (size_t)w * DD * DD;
        #pragma unroll
        for (int rep = 0; rep < 32; rep++) {
            int i = rep * 128 + t;
            int k = i >> 5, j = i & 31;
            st[j][k] = W[(size_t)k * DD + n0 + j];
        }
        __syncthreads();
        #pragma unroll
        for (int rep = 0; rep < 32; rep++) {
            int i = rep * 128 + t;
            int nl = i >> 7, k = i & 127;
            T[(size_t)(n0 + nl) * DD + k] = __float2bfloat16(st[nl][k]);
        }
        return;
    }
    for (int i = t; i < 384; i += 128)
        b3[i] = (i < 128) ? bq[i] : (i < 256) ? bk[i - 128] : bv[i - 256];
}

// =====================================================================
// K2: bf16 tensor-core GEMM (warp tile 32x32, CTA 64x128).
// bf16 output: double-buffered A + direct bf16x2 stores.
// fp32 output: single A buffer, next-A cp.async issued BEFORE the staged
//   epilogue (load hides under the 32KB coalesced store phase).
// =====================================================================
template<typename OutT>
__global__ __launch_bounds__(256, 3)
void mma_gemm(const __nv_bfloat16* __restrict__ A, const __nv_bfloat16* __restrict__ B,
              const float* __restrict__ bias, OutT* __restrict__ C,
              long long ldc, int nvalid, int m_iters)
{
    extern __shared__ char sm[];
    char* sB    = sm;
    char* sAbuf = sB + TILE_B_SMEM;                 // 2 x TILE_A_SMEM region
    float* sbias = (float*)(sAbuf + 2 * TILE_A_SMEM);
    float* sC    = (float*)(sAbuf + TILE_A_SMEM);   // fp32 path: 32x132 staging

    const int t = threadIdx.x;
    const int lane = t & 31;
    const int wid  = t >> 5;
    const int warp_m = wid >> 2;        // 0..1 (32 rows each)
    const int warp_n = wid & 3;         // 0..3 (32 cols each)
    const int n0 = blockIdx.x * 128;

    const uint32_t sBu = cvta_smem(sB);
    const uint32_t sAu = cvta_smem(sAbuf);

    // ---- async load B tile + first A tile ----
    {
        const __nv_bfloat16* gB = B + (size_t)n0 * DD;
        #pragma unroll
        for (int i = 0; i < 8; i++) {
            int idx = i * 256 + t;
            int r = idx >> 4, seg = idx & 15;
            cp16(sBu + r * ROWB + seg * 16, gB + (size_t)r * DD + seg * 8);
        }
        const __nv_bfloat16* gA = A + (size_t)(blockIdx.y * m_iters) * 64 * DD;
        #pragma unroll
        for (int i = 0; i < 4; i++) {
            int idx = i * 256 + t;
            int r = idx >> 4, seg = idx & 15;
            cp16(sAu + r * ROWB + seg * 16, gA + (size_t)r * DD + seg * 8);
        }
        CP_COMMIT();
        if (t < 128) sbias[t] = (n0 + t < nvalid) ? bias[n0 + t] : 0.f;
        CP_WAIT0();
    }
    __syncthreads();

    // ---- ldmatrix lane addressing ----
    const int quad = lane >> 3, j = lane & 7;
    const uint32_t aLane = (uint32_t)((warp_m * 32 + (quad & 1) * 8 + j) * ROWB
                                      + (quad >> 1) * 16);
    const uint32_t bLane = sBu
                         + (uint32_t)((warp_n * 32 + (quad >> 1) * 8 + j) * ROWB
                                      + (quad & 1) * 16);

    const int frow = lane >> 2;
    int cur = 0;

    for (int iter = 0; iter < m_iters; iter++) {
        const int m0 = (blockIdx.y * m_iters + iter) * 64;
        const bool has_next = (iter + 1 < m_iters);

        if constexpr (sizeof(OutT) == 2) {
            if (has_next) {
                const __nv_bfloat16* gn = A + (size_t)(m0 + 64) * DD;
                const uint32_t dst = sAu + (uint32_t)((cur ^ 1) * TILE_A_SMEM);
                #pragma unroll
                for (int i = 0; i < 4; i++) {
                    int idx = i * 256 + t;
                    int r = idx >> 4, seg = idx & 15;
                    cp16(dst + r * ROWB + seg * 16, gn + (size_t)r * DD + seg * 8);
                }
                CP_COMMIT();
            }
        }

        const uint32_t aAddr = aLane + sAu + (uint32_t)(cur * TILE_A_SMEM);

        float acc[2][4][4];
        #pragma unroll
        for (int mi = 0; mi < 2; mi++)
            #pragma unroll
            for (int ni = 0; ni < 4; ni++)
                #pragma unroll
                for (int e = 0; e < 4; e++) acc[mi][ni][e] = 0.f;

        #pragma unroll
        for (int kb = 0; kb < 8; kb++) {
            const uint32_t ko = kb * 32;
            uint32_t a0[4], a1[4], b01[4], b23[4];
            ldsm_x4(a0,  aAddr + ko);
            ldsm_x4(a1,  aAddr + ko + 16 * ROWB);
            ldsm_x4(b01, bLane + ko);
            ldsm_x4(b23, bLane + ko + 16 * ROWB);
            mma_bf16(acc[0][0], a0, b01);  mma_bf16(acc[0][1], a0, b01 + 2);
            mma_bf16(acc[0][2], a0, b23);  mma_bf16(acc[0][3], a0, b23 + 2);
            mma_bf16(acc[1][0], a1, b01);  mma_bf16(acc[1][1], a1, b01 + 2);
            mma_bf16(acc[1][2], a1, b23);  mma_bf16(acc[1][3], a1, b23 + 2);
        }

        if constexpr (sizeof(OutT) == 2) {
            #pragma unroll
            for (int mi = 0; mi < 2; mi++) {
                const int r0 = m0 + warp_m * 32 + mi * 16 + frow;
                OutT* crow0 = C + (long long)r0 * ldc;
                OutT* crow1 = C + (long long)(r0 + 8) * ldc;
                #pragma unroll
                for (int ni = 0; ni < 4; ni++) {
                    const int nl = warp_n * 32 + ni * 8 + (lane & 3) * 2;
                    const int n  = n0 + nl;
                    const float b0 = sbias[nl], b1 = sbias[nl + 1];
                    __nv_bfloat162 s0, s1;
                    s0.x = __float2bfloat16(acc[mi][ni][0] + b0);
                    s0.y = __float2bfloat16(acc[mi][ni][1] + b1);
                    s1.x = __float2bfloat16(acc[mi][ni][2] + b0);
                    s1.y = __float2bfloat16(acc[mi][ni][3] + b1);
                    *reinterpret_cast<__nv_bfloat162*>(crow0 + n) = s0;
                    *reinterpret_cast<__nv_bfloat162*>(crow1 + n) = s1;
                }
            }
            if (has_next) {
                CP_WAIT0();
                __syncthreads();
                cur ^= 1;
            }
        } else {
            // ---- issue next-A load NOW (hides under epilogue stores) ----
            if (has_next) {
                __syncthreads();   // all ldmatrix reads of sA complete
                const __nv_bfloat16* gn = A + (size_t)(m0 + 64) * DD;
                #pragma unroll
                for (int i = 0; i < 4; i++) {
                    int idx = i * 256 + t;
                    int r = idx >> 4, seg = idx & 15;
                    cp16(sAu + r * ROWB + seg * 16, gn + (size_t)r * DD + seg * 8);
                }
                CP_COMMIT();
            }
            // ---- fp32 epilogue: smem-staged (float2), coalesced stores ----
            #pragma unroll
            for (int h = 0; h < 2; h++) {
                __syncthreads();
                if (warp_m == h) {
                    #pragma unroll
                    for (int mi = 0; mi < 2; mi++) {
                        const int lr = mi * 16 + frow;
                        #pragma unroll
                        for (int ni = 0; ni < 4; ni++) {
                            const int nl = warp_n * 32 + ni * 8 + (lane & 3) * 2;
                            const float b0 = sbias[nl], b1 = sbias[nl + 1];
                            *reinterpret_cast<float2*>(&sC[lr * CSTAGE_LD + nl]) =
                                make_float2(acc[mi][ni][0] + b0, acc[mi][ni][1] + b1);
                            *reinterpret_cast<float2*>(&sC[(lr + 8) * CSTAGE_LD + nl]) =
                                make_float2(acc[mi][ni][2] + b0, acc[mi][ni][3] + b1);
                        }
                    }
                }
                __syncthreads();
                const int grow0 = m0 + h * 32;
                #pragma unroll
                for (int i = 0; i < 16; i++) {
                    int e  = i * 256 + t;
                    int lr = e >> 7, c = e & 127;
                    int gc = n0 + c;
                    if (gc < nvalid)
                        ((float*)C)[(long long)(grow0 + lr) * ldc + gc] =
                            sC[lr * CSTAGE_LD + c];
                }
            }
            if (has_next) {
                CP_WAIT0();
                __syncthreads();
            }
        }
    }
}

// =====================================================================
// K3: attention, one block per (b,h); transposed Q/K layout +
// 4x4 register tiling; FMA-based exp (no MUFU bottleneck).
// =====================================================================
__global__ __launch_bounds__(256)
void attn_kernel(const __nv_bfloat16* __restrict__ qkv, const int* __restrict__ seq,
                 __nv_bfloat16* __restrict__ av)
{
    __shared__ float sqT[32][56];     // Q^T [d][s]
    __shared__ float skT[32][56];     // K^T [d][s]
    __shared__ float sv [SS][36];     // V   [s][d]
    __shared__ float sc [52][56];     // scores/probs [qi][kj]
    __shared__ int   spad[52];

    int b = blockIdx.x >> 2;
    int h = blockIdx.x & 3;
    int tid = threadIdx.x;

    for (int idx = tid; idx < SS * 4; idx += 256) {
        int s = idx >> 2, c = idx & 3;
        size_t base = ((size_t)(b * SS + s)) * 384 + h * 32 + c * 8;
        uint4 q4 = *reinterpret_cast<const uint4*>(qkv + base);
        uint4 k4 = *reinterpret_cast<const uint4*>(qkv + base + 128);
        uint4 v4 = *reinterpret_cast<const uint4*>(qkv + base + 256);
        const uint32_t* qw = (const uint32_t*)&q4;
        const uint32_t* kw = (const uint32_t*)&k4;
        const uint32_t* vw = (const uint32_t*)&v4;
        #pragma unroll
        for (int w = 0; w < 4; w++) {
            float2 qf = __bfloat1622float2(*(const __nv_bfloat162*)&qw[w]);
            float2 kf = __bfloat1622float2(*(const __nv_bfloat162*)&kw[w]);
            float2 vf = __bfloat1622float2(*(const __nv_bfloat162*)&vw[w]);
            int d = c * 8 + w * 2;
            sqT[d][s] = qf.x;  sqT[d + 1][s] = qf.y;
            skT[d][s] = kf.x;  skT[d + 1][s] = kf.y;
            sv[s][d]  = vf.x;  sv[s][d + 1]  = vf.y;
        }
    }
    if (tid < 52) spad[tid] = (tid < SS) ? (seq[b * SS + tid] == 0) : 1;
    __syncthreads();

    // ---- scores: 13x13 grid of 4x4 tiles (169 threads) ----
    if (tid < 169) {
        int qi0 = (tid / 13) * 4;
        int kj0 = (tid % 13) * 4;
        float acc[4][4];
        #pragma unroll
        for (int i = 0; i < 4; i++)
            #pragma unroll
            for (int jj = 0; jj < 4; jj++) acc[i][jj] = 0.f;
        #pragma unroll
        for (int d = 0; d < 32; d++) {
            float4 qv = *reinterpret_cast<const float4*>(&sqT[d][qi0]);
            float4 kv = *reinterpret_cast<const float4*>(&skT[d][kj0]);
            const float* qa = (const float*)&qv;
            const float* ka = (const float*)&kv;
            #pragma unroll
            for (int i = 0; i < 4; i++)
                #pragma unroll
                for (int jj = 0; jj < 4; jj++)
                    acc[i][jj] += qa[i] * ka[jj];
        }
        #pragma unroll
        for (int i = 0; i < 4; i++) {
            float4 row;
            float* ra = (float*)&row;
            #pragma unroll
            for (int jj = 0; jj < 4; jj++) {
                float v = acc[i][jj] * (1.0f / 32.0f);
                ra[jj] = (spad[qi0 + i] | spad[kj0 + jj]) ? NEGV : v;
            }
            *reinterpret_cast<float4*>(&sc[qi0 + i][kj0]) = row;
        }
    }
    __syncthreads();

    // ---- row softmax: one warp per row; FMA-based exp ----
    int wid = tid >> 5, lane = tid & 31;
    for (int r = wid; r < SS; r += 8) {
        float m = -INFINITY;
        for (int j = lane; j < SS; j += 32) m = fmaxf(m, sc[r][j]);
        #pragma unroll
        for (int o = 16; o; o >>= 1) m = fmaxf(m, __shfl_xor_sync(0xffffffffu, m, o));
        float sum = 0.f;
        for (int j = lane; j < SS; j += 32) {
            float e = fexp(sc[r][j] - m);
            sc[r][j] = e;
            sum += e;
        }
        #pragma unroll
        for (int o = 16; o; o >>= 1) sum += __shfl_xor_sync(0xffffffffu, sum, o);
        float inv = 1.0f / sum;
        for (int j = lane; j < SS; j += 32) sc[r][j] *= inv;
    }
    __syncthreads();

    // ---- AV: 13x8 grid of 4(s)x4(d) tiles (104 threads) ----
    if (tid < 104) {
        int s0 = (tid / 8) * 4;
        int d0 = (tid % 8) * 4;
        float acc[4][4];
        #pragma unroll
        for (int i = 0; i < 4; i++)
            #pragma unroll
            for (int jj = 0; jj < 4; jj++) acc[i][jj] = 0.f;
        for (int j = 0; j < SS; j++) {
            float4 vv = *reinterpret_cast<const float4*>(&sv[j][d0]);
            const float* va = (const float*)&vv;
            #pragma unroll
            for (int i = 0; i < 4; i++) {
                float p = sc[s0 + i][j];
                #pragma unroll
                for (int jj = 0; jj < 4; jj++)
                    acc[i][jj] += p * va[jj];
            }
        }
        #pragma unroll
        for (int i = 0; i < 4; i++) {
            int s = s0 + i;
            if (s < SS) {
                size_t o = ((size_t)(b * SS + s)) * DD + h * 32 + d0;
                __nv_bfloat162 p0, p1;
                p0.x = __float2bfloat16(acc[i][0]); p0.y = __float2bfloat16(acc[i][1]);
                p1.x = __float2bfloat16(acc[i][2]); p1.y = __float2bfloat16(acc[i][3]);
                *reinterpret_cast<__nv_bfloat162*>(av + o)     = p0;
                *reinterpret_cast<__nv_bfloat162*>(av + o + 2) = p1;
            }
        }
    }
}

// =====================================================================
// K4: SelfEnc pooling, one block per batch; bf16 in, bf16 out
// =====================================================================
__global__ __launch_bounds__(128)
void pool_kernel(const __nv_bfloat16* __restrict__ enc, const float* __restrict__ w_enc,
                 const float* __restrict__ b_enc, __nv_bfloat16* __restrict__ p)
{
    __shared__ float se[SS][DD];
    __shared__ float swt[SS];
    __shared__ float swe[DD];
    int b = blockIdx.x;
    int tid = threadIdx.x;

    swe[tid] = w_enc[tid];
    for (int idx = tid; idx < SS * DD / 2; idx += 128) {
        __nv_bfloat162 v = *reinterpret_cast<const __nv_bfloat162*>(
            enc + (size_t)b * SS * DD + idx * 2);
        float2 f = __bfloat1622float2(v);
        int r = (idx * 2) >> 7, c = (idx * 2) & 127;
        se[r][c] = f.x;
        se[r][c + 1] = f.y;
    }
    __syncthreads();

    int wid = tid >> 5, lane = tid & 31;
    for (int s = wid; s < SS; s += 4) {
        float acc = 0.f;
        #pragma unroll
        for (int d = lane; d < DD; d += 32) acc += se[s][d] * swe[d];
        #pragma unroll
        for (int o = 16; o; o >>= 1) acc += __shfl_xor_sync(0xffffffffu, acc, o);
        if (lane == 0) swt[s] = acc + b_enc[0];
    }
    __syncthreads();

    float acc = 0.f;
    #pragma unroll
    for (int s = 0; s < SS; s++) acc += swt[s] * se[s][tid];
    p[b * DD + tid] = __float2bfloat16(acc);
}

// =====================================================================
// K5: consumed-item mask scatter
// =====================================================================
__global__ void mask_kernel(const int* __restrict__ seq, float* __restrict__ out)
{
    int b = blockIdx.x;
    int s = threadIdx.x;
    if (s < SS) out[(size_t)b * VV + seq[b * SS + s]] = NEGV;
}

// =====================================================================
// launch
// =====================================================================
extern "C" void kernel_launch(void* const* d_in, const int* in_sizes, int n_in,
                              void* d_out, int out_size)
{
    const int*   seq    = (const int*)  d_in[0];
    const int*   subty  = (const int*)  d_in[1];
    const float* emb    = (const float*)d_in[2];
    const float* sgt    = (const float*)d_in[3];
    const float* wq     = (const float*)d_in[4];
    const float* bq     = (const float*)d_in[5];
    const float* wk     = (const float*)d_in[6];
    const float* bk     = (const float*)d_in[7];
    const float* wv     = (const float*)d_in[8];
    const float* bv     = (const float*)d_in[9];
    const float* wo     = (const float*)d_in[10];
    const float* bo     = (const float*)d_in[11];
    const float* w_enc  = (const float*)d_in[12];
    const float* b_enc  = (const float*)d_in[13];
    const float* wscore = (const float*)d_in[14];
    const float* bscore = (const float*)d_in[15];
    float* out = (float*)d_out;

    __nv_bfloat16 *x, *qkv, *av, *enc, *p, *ws, *w4;
    float *b3;
    cudaGetSymbolAddress((void**)&x,    g_x);
    cudaGetSymbolAddress((void**)&qkv,  g_qkv);
    cudaGetSymbolAddress((void**)&av,   g_av);
    cudaGetSymbolAddress((void**)&enc,  g_enc);
    cudaGetSymbolAddress((void**)&p,    g_p);
    cudaGetSymbolAddress((void**)&ws,   g_ws);
    cudaGetSymbolAddress((void**)&w4,   g_w4);
    cudaGetSymbolAddress((void**)&b3,   g_b3);

    const int GEMM_SMEM = TILE_B_SMEM + 2 * TILE_A_SMEM + 512;   // 70144
    cudaFuncSetAttribute((const void*)mma_gemm<__nv_bfloat16>,
                         cudaFuncAttributeMaxDynamicSharedMemorySize, GEMM_SMEM);
    cudaFuncSetAttribute((const void*)mma_gemm<float>,
                         cudaFuncAttributeMaxDynamicSharedMemorySize, GEMM_SMEM);

    // 1) merged prep: embed+PE, weight transposes, bias concat
    prep_kernel<<<PREP_EMBED + PREP_WSV + 16 + 1, 128>>>(
        seq, subty, emb, sgt, wscore, wq, wk, wv, wo, bq, bk, bv,
        x, ws, w4, b3);

    // 2) fused QKV projection (bf16 out): grid (3, 98) x m_iters 8
    mma_gemm<__nv_bfloat16><<<dim3(3, BS / 64 / 8), 256, GEMM_SMEM>>>(
        x, w4, b3, qkv, 384, 384, 8);

    // 3) attention (bf16 in/out, register-tiled, FMA exp)
    attn_kernel<<<BB * HH, 256>>>(qkv, seq, av);

    // 4) output projection (bf16 out): grid (1, 98) x m_iters 8
    mma_gemm<__nv_bfloat16><<<dim3(1, BS / 64 / 8), 256, GEMM_SMEM>>>(
        av, w4 + 3 * DD * DD, bo, enc, DD, DD, 8);

    // 5) pooling (bf16 in, bf16 out)
    pool_kernel<<<BB, 128>>>(enc, w_enc, b_enc, p);

    // 6) novelty scores: grid (782, 2) x m_iters 8 = 16 M-tiles (FULL coverage)
    mma_gemm<float><<<dim3(VV_PAD / 128, 2), 256, GEMM_SMEM>>>(
        p, ws, bscore, out, (long long)VV, VV, 8);

    // 7) consumed mask
    mask_kernel<<<BB, 64>>>(seq, out);
}